// round 1
// baseline (speedup 1.0000x reference)
#include <cuda_runtime.h>

#define D_MODEL  2048
#define KV_DIM   512
#define SEQ      1024
#define BATCH    4
#define NTOK     (BATCH * SEQ)   // 4096
#define NHEADS   32
#define HEAD_DIM 64

// ---------------- scratch (no cudaMalloc allowed) ----------------
__device__ float g_q[NTOK * D_MODEL];    // 32 MB
__device__ float g_k[NTOK * KV_DIM];     //  8 MB
__device__ float g_v[NTOK * KV_DIM];     //  8 MB
__device__ float g_ctx[NTOK * D_MODEL];  // 32 MB

// ================= SGEMM: C[M,N] = A[M,K] @ B[K,N] + bias =================
// BM=BN=128, BK=16, 256 threads, 8x8 register tile.
__global__ __launch_bounds__(256) void gemm_bias_kernel(
    const float* __restrict__ A, const float* __restrict__ B,
    const float* __restrict__ bias, float* __restrict__ C,
    int N, int K)
{
    __shared__ float Ast[16][132];   // A tile transposed: Ast[k][m], pad 132 for conflict-free
    __shared__ float Bs[16][128];    // B tile natural:    Bs[k][n]

    const int t  = threadIdx.x;
    const int tx = t & 15;           // 0..15 -> n
    const int ty = t >> 4;           // 0..15 -> m
    const int row0 = blockIdx.y * 128;
    const int col0 = blockIdx.x * 128;

    float acc[8][8];
#pragma unroll
    for (int i = 0; i < 8; i++)
#pragma unroll
        for (int j = 0; j < 8; j++) acc[i][j] = 0.0f;

    for (int k0 = 0; k0 < K; k0 += 16) {
        // ---- load A tile 128x16 (transposed into Ast) ----
#pragma unroll
        for (int it = 0; it < 2; it++) {
            int idx = t + it * 256;          // 0..511 float4s
            int r   = idx >> 2;              // 0..127
            int c4  = idx & 3;               // 0..3
            float4 v = *(const float4*)(A + (size_t)(row0 + r) * K + k0 + c4 * 4);
            Ast[c4 * 4 + 0][r] = v.x;
            Ast[c4 * 4 + 1][r] = v.y;
            Ast[c4 * 4 + 2][r] = v.z;
            Ast[c4 * 4 + 3][r] = v.w;
        }
        // ---- load B tile 16x128 ----
#pragma unroll
        for (int it = 0; it < 2; it++) {
            int idx = t + it * 256;          // 0..511 float4s
            int r   = idx >> 5;              // 0..15
            int c4  = idx & 31;              // 0..31
            *(float4*)(&Bs[r][c4 * 4]) =
                *(const float4*)(B + (size_t)(k0 + r) * N + col0 + c4 * 4);
        }
        __syncthreads();

#pragma unroll
        for (int kk = 0; kk < 16; kk++) {
            float a[8], b[8];
            *(float4*)(a)     = *(float4*)(&Ast[kk][ty * 8]);
            *(float4*)(a + 4) = *(float4*)(&Ast[kk][ty * 8 + 4]);
            *(float4*)(b)     = *(float4*)(&Bs[kk][tx * 8]);
            *(float4*)(b + 4) = *(float4*)(&Bs[kk][tx * 8 + 4]);
#pragma unroll
            for (int i = 0; i < 8; i++)
#pragma unroll
                for (int j = 0; j < 8; j++) acc[i][j] += a[i] * b[j];
        }
        __syncthreads();
    }

    // ---- epilogue with bias ----
#pragma unroll
    for (int i = 0; i < 8; i++) {
        int row = row0 + ty * 8 + i;
#pragma unroll
        for (int j4 = 0; j4 < 2; j4++) {
            int col = col0 + tx * 8 + j4 * 4;
            float4 bv = *(const float4*)(bias + col);
            float4 o;
            o.x = acc[i][j4 * 4 + 0] + bv.x;
            o.y = acc[i][j4 * 4 + 1] + bv.y;
            o.z = acc[i][j4 * 4 + 2] + bv.z;
            o.w = acc[i][j4 * 4 + 3] + bv.w;
            *(float4*)(C + (size_t)row * N + col) = o;
        }
    }
}

// ================= Flash attention =================
// grid: (S/64, NHEADS, BATCH), 256 threads.
// Per CTA: 64 q-rows of head h; loop over 16 k-tiles of 64 rows.
// Thread (ty 0..15, tx 0..15): score sub-tile rows ty*4..+3, cols tx*4..+3;
// output sub-tile rows ty*4..+3, d-cols tx*4..+3.
__global__ __launch_bounds__(256) void attn_kernel(float* __restrict__ ctx)
{
    __shared__ float Qs[64 * 64];   // Qs[r][d], pre-scaled by 1/sqrt(d)
    __shared__ float KP[64 * 64];   // phase 1: K transposed [d][c]; phase 2: P [r][c]
    __shared__ float Vs[64 * 64];   // Vs[c][d]

    const int t  = threadIdx.x;
    const int tx = t & 15;
    const int ty = t >> 4;
    const int qt = blockIdx.x;
    const int h  = blockIdx.y;
    const int b  = blockIdx.z;
    const int kvh = h >> 2;         // repeat_interleave: head h -> kv head h/4

    const float* qbase = g_q + (size_t)(b * SEQ + qt * 64) * D_MODEL + h * HEAD_DIM;
    const float* kbase = g_k + (size_t)(b * SEQ) * KV_DIM + kvh * HEAD_DIM;
    const float* vbase = g_v + (size_t)(b * SEQ) * KV_DIM + kvh * HEAD_DIM;

    // load Q tile (scaled by 0.125 = 1/sqrt(64))
#pragma unroll
    for (int it = 0; it < 4; it++) {
        int idx = t + it * 256;      // 0..1023 float4s
        int r  = idx >> 4;
        int d4 = idx & 15;
        float4 v = *(const float4*)(qbase + (size_t)r * D_MODEL + d4 * 4);
        v.x *= 0.125f; v.y *= 0.125f; v.z *= 0.125f; v.w *= 0.125f;
        *(float4*)&Qs[r * 64 + d4 * 4] = v;
    }

    float m[4], l[4], o[4][4];
#pragma unroll
    for (int i = 0; i < 4; i++) {
        m[i] = -1e30f; l[i] = 0.0f;
#pragma unroll
        for (int j = 0; j < 4; j++) o[i][j] = 0.0f;
    }

    for (int kt = 0; kt < SEQ / 64; kt++) {
        __syncthreads();   // previous-iter P/V reads done before overwrite
        const float* kb = kbase + (size_t)kt * 64 * KV_DIM;
        const float* vb = vbase + (size_t)kt * 64 * KV_DIM;
#pragma unroll
        for (int it = 0; it < 1; it++) { }
#pragma unroll
        for (int it = 0; it < 1; it++) { }
        // load K (transposed) and V tiles
#pragma unroll
        for (int it = 0; it < 1; it++) {
            int idx = t;                         // 256 threads x 1 float4 each -> 256 f4 = 1024 floats... need 1024 f4
        }
#pragma unroll
        for (int it = 0; it < 4; it++) {
            int idx = t + it * 256;              // 0..1023 float4s
            int c  = idx >> 4;
            int d0 = (idx & 15) * 4;
            float4 kv4 = *(const float4*)(kb + (size_t)c * KV_DIM + d0);
            KP[(d0 + 0) * 64 + c] = kv4.x;
            KP[(d0 + 1) * 64 + c] = kv4.y;
            KP[(d0 + 2) * 64 + c] = kv4.z;
            KP[(d0 + 3) * 64 + c] = kv4.w;
            *(float4*)&Vs[c * 64 + d0] = *(const float4*)(vb + (size_t)c * KV_DIM + d0);
        }
        __syncthreads();

        // ---- scores s[i][j] = sum_d Qs[row][d] * K[col][d] (Q pre-scaled) ----
        float s[4][4];
#pragma unroll
        for (int i = 0; i < 4; i++)
#pragma unroll
            for (int j = 0; j < 4; j++) s[i][j] = 0.0f;

#pragma unroll 16
        for (int d = 0; d < 64; d++) {
            float4 k4 = *(float4*)&KP[d * 64 + tx * 4];
            float q0 = Qs[(ty * 4 + 0) * 64 + d];
            float q1 = Qs[(ty * 4 + 1) * 64 + d];
            float q2 = Qs[(ty * 4 + 2) * 64 + d];
            float q3 = Qs[(ty * 4 + 3) * 64 + d];
            s[0][0] += q0 * k4.x; s[0][1] += q0 * k4.y; s[0][2] += q0 * k4.z; s[0][3] += q0 * k4.w;
            s[1][0] += q1 * k4.x; s[1][1] += q1 * k4.y; s[1][2] += q1 * k4.z; s[1][3] += q1 * k4.w;
            s[2][0] += q2 * k4.x; s[2][1] += q2 * k4.y; s[2][2] += q2 * k4.z; s[2][3] += q2 * k4.w;
            s[3][0] += q3 * k4.x; s[3][1] += q3 * k4.y; s[3][2] += q3 * k4.z; s[3][3] += q3 * k4.w;
        }

        // ---- online softmax (register + shuffle over the 16 tx lanes) ----
#pragma unroll
        for (int i = 0; i < 4; i++) {
            float rm = fmaxf(fmaxf(s[i][0], s[i][1]), fmaxf(s[i][2], s[i][3]));
#pragma unroll
            for (int off = 8; off > 0; off >>= 1)
                rm = fmaxf(rm, __shfl_xor_sync(0xffffffffu, rm, off));
            float mn   = fmaxf(m[i], rm);
            float corr = __expf(m[i] - mn);
            s[i][0] = __expf(s[i][0] - mn);
            s[i][1] = __expf(s[i][1] - mn);
            s[i][2] = __expf(s[i][2] - mn);
            s[i][3] = __expf(s[i][3] - mn);
            float rs = s[i][0] + s[i][1] + s[i][2] + s[i][3];
#pragma unroll
            for (int off = 8; off > 0; off >>= 1)
                rs += __shfl_xor_sync(0xffffffffu, rs, off);
            l[i] = l[i] * corr + rs;
            m[i] = mn;
            o[i][0] *= corr; o[i][1] *= corr; o[i][2] *= corr; o[i][3] *= corr;
        }

        __syncthreads();   // everyone done reading KP as K
        // store P into KP
#pragma unroll
        for (int i = 0; i < 4; i++) {
            float4 pv;
            pv.x = s[i][0]; pv.y = s[i][1]; pv.z = s[i][2]; pv.w = s[i][3];
            *(float4*)&KP[(ty * 4 + i) * 64 + tx * 4] = pv;
        }
        __syncthreads();

        // ---- O += P @ V ----
#pragma unroll 16
        for (int c = 0; c < 64; c++) {
            float4 v4 = *(float4*)&Vs[c * 64 + tx * 4];
            float p0 = KP[(ty * 4 + 0) * 64 + c];
            float p1 = KP[(ty * 4 + 1) * 64 + c];
            float p2 = KP[(ty * 4 + 2) * 64 + c];
            float p3 = KP[(ty * 4 + 3) * 64 + c];
            o[0][0] += p0 * v4.x; o[0][1] += p0 * v4.y; o[0][2] += p0 * v4.z; o[0][3] += p0 * v4.w;
            o[1][0] += p1 * v4.x; o[1][1] += p1 * v4.y; o[1][2] += p1 * v4.z; o[1][3] += p1 * v4.w;
            o[2][0] += p2 * v4.x; o[2][1] += p2 * v4.y; o[2][2] += p2 * v4.z; o[2][3] += p2 * v4.w;
            o[3][0] += p3 * v4.x; o[3][1] += p3 * v4.y; o[3][2] += p3 * v4.z; o[3][3] += p3 * v4.w;
        }
    }

    // ---- write ctx in [B, S, H*d] layout ----
    float* cb = ctx + (size_t)(b * SEQ + qt * 64) * D_MODEL + h * HEAD_DIM;
#pragma unroll
    for (int i = 0; i < 4; i++) {
        float inv = 1.0f / l[i];
        float4 ov;
        ov.x = o[i][0] * inv; ov.y = o[i][1] * inv; ov.z = o[i][2] * inv; ov.w = o[i][3] * inv;
        *(float4*)(cb + (size_t)(ty * 4 + i) * D_MODEL + tx * 4) = ov;
    }
}

// ================= launch =================
extern "C" void kernel_launch(void* const* d_in, const int* in_sizes, int n_in,
                              void* d_out, int out_size)
{
    const float* x  = (const float*)d_in[0];
    const float* Wq = (const float*)d_in[1];
    const float* bq = (const float*)d_in[2];
    const float* Wk = (const float*)d_in[3];
    const float* bk = (const float*)d_in[4];
    const float* Wv = (const float*)d_in[5];
    const float* bv = (const float*)d_in[6];
    const float* Wo = (const float*)d_in[7];
    const float* bo = (const float*)d_in[8];
    float* out = (float*)d_out;

    float *qb, *kb, *vb, *cb;
    cudaGetSymbolAddress((void**)&qb, g_q);
    cudaGetSymbolAddress((void**)&kb, g_k);
    cudaGetSymbolAddress((void**)&vb, g_v);
    cudaGetSymbolAddress((void**)&cb, g_ctx);

    dim3 blk(256);
    // projections
    gemm_bias_kernel<<<dim3(D_MODEL / 128, NTOK / 128), blk>>>(x, Wq, bq, qb, D_MODEL, D_MODEL);
    gemm_bias_kernel<<<dim3(KV_DIM  / 128, NTOK / 128), blk>>>(x, Wk, bk, kb, KV_DIM,  D_MODEL);
    gemm_bias_kernel<<<dim3(KV_DIM  / 128, NTOK / 128), blk>>>(x, Wv, bv, vb, KV_DIM,  D_MODEL);
    // attention
    attn_kernel<<<dim3(SEQ / 64, NHEADS, BATCH), blk>>>(cb);
    // output projection
    gemm_bias_kernel<<<dim3(D_MODEL / 128, NTOK / 128), blk>>>(cb, Wo, bo, out, D_MODEL, D_MODEL);
}